// round 1
// baseline (speedup 1.0000x reference)
#include <cuda_runtime.h>
#include <cstdint>

#define Bn   2048
#define Nin  512
#define Tn   100
#define H1n  512
#define H2n  256
#define On   5
#define Mn   (Tn*Bn)   // 204800 rows = (t,b)

// Scratch (static device globals: allocation-free per harness rules)
__device__ float g_xT[(size_t)Mn * Nin];   // xT[(t*B+b)*N + n]
__device__ float g_h1[(size_t)Mn * H1n];   // h1 then (in-place) s1
__device__ float g_h2[(size_t)Mn * H2n];   // h2 then (in-place) s2

// ---------------- packed f32x2 helpers (sm_103a full-rate fp32) ------------
__device__ __forceinline__ unsigned long long pk2(float lo, float hi) {
    unsigned long long r;
    asm("mov.b64 %0, {%1, %2};" : "=l"(r) : "f"(lo), "f"(hi));
    return r;
}
__device__ __forceinline__ void upk2(unsigned long long v, float& lo, float& hi) {
    asm("mov.b64 {%0, %1}, %2;" : "=f"(lo), "=f"(hi) : "l"(v));
}
__device__ __forceinline__ unsigned long long fma2(unsigned long long a,
                                                   unsigned long long b,
                                                   unsigned long long c) {
    unsigned long long d;
    asm("fma.rn.f32x2 %0, %1, %2, %3;" : "=l"(d) : "l"(a), "l"(b), "l"(c));
    return d;
}

// ---------------- transpose x (B,N,T) -> xT[(t*B+b)*N + n] -----------------
__global__ void k_transpose(const float* __restrict__ x) {
    __shared__ float tile[32][33];
    int b  = blockIdx.x;
    int n0 = blockIdx.y * 32;
    int t0 = blockIdx.z * 32;
    int tx = threadIdx.x, ty = threadIdx.y;   // 32 x 8
#pragma unroll
    for (int i = 0; i < 4; i++) {
        int n = n0 + ty + i * 8, t = t0 + tx;
        if (t < Tn) tile[ty + i * 8][tx] = x[((size_t)b * Nin + n) * Tn + t];
    }
    __syncthreads();
#pragma unroll
    for (int i = 0; i < 4; i++) {
        int t = t0 + ty + i * 8, n = n0 + tx;
        if (t < Tn) g_xT[((size_t)t * Bn + b) * Nin + n] = tile[tx][ty + i * 8];
    }
}

// ---------------- SGEMM (NT): C[m][n] = sum_k A[m][k]*Bw[n][k] + bias[n] ---
// M = 204800 (exact multiple of 128), K = 512, N in {512, 256}.
// 128x128 tile, BK=16, 256 threads, 8x8 microtile via fma.rn.f32x2.
__global__ __launch_bounds__(256, 2)
void k_gemm(const float* __restrict__ Bw, const float* __restrict__ bias,
            int ldc, int mode) {
    const float* A;
    float* C;
    if (mode == 1) { A = g_xT; C = g_h1; } else { A = g_h1; C = g_h2; }

    __shared__ float As[16][132];
    __shared__ float Bs[16][132];

    int tid = threadIdx.x;
    int nt = blockIdx.x, mt = blockIdx.y;
    const float* Ab = A  + (size_t)mt * 128 * 512;
    const float* Bb = Bw + (size_t)nt * 128 * 512;

    int lr = tid >> 2;          // 0..63
    int lc = (tid & 3) << 2;    // 0,4,8,12
    int tm = tid >> 4;          // 0..15
    int tn = tid & 15;          // 0..15

    unsigned long long c2[8][4];
#pragma unroll
    for (int m = 0; m < 8; m++)
#pragma unroll
        for (int p = 0; p < 4; p++) c2[m][p] = 0ull;

    float4 fa0, fa1, fb0, fb1;
    // prologue: load k-tile 0
    fa0 = *(const float4*)(Ab + (size_t)lr * 512 + lc);
    fa1 = *(const float4*)(Ab + (size_t)(lr + 64) * 512 + lc);
    fb0 = *(const float4*)(Bb + (size_t)lr * 512 + lc);
    fb1 = *(const float4*)(Bb + (size_t)(lr + 64) * 512 + lc);
    As[lc + 0][lr] = fa0.x; As[lc + 1][lr] = fa0.y; As[lc + 2][lr] = fa0.z; As[lc + 3][lr] = fa0.w;
    As[lc + 0][lr + 64] = fa1.x; As[lc + 1][lr + 64] = fa1.y; As[lc + 2][lr + 64] = fa1.z; As[lc + 3][lr + 64] = fa1.w;
    Bs[lc + 0][lr] = fb0.x; Bs[lc + 1][lr] = fb0.y; Bs[lc + 2][lr] = fb0.z; Bs[lc + 3][lr] = fb0.w;
    Bs[lc + 0][lr + 64] = fb1.x; Bs[lc + 1][lr + 64] = fb1.y; Bs[lc + 2][lr + 64] = fb1.z; Bs[lc + 3][lr + 64] = fb1.w;
    __syncthreads();

    for (int kt = 0; kt < 32; kt++) {
        if (kt < 31) {  // prefetch next k-tile into registers (overlaps compute)
            int ko = (kt + 1) * 16 + lc;
            fa0 = *(const float4*)(Ab + (size_t)lr * 512 + ko);
            fa1 = *(const float4*)(Ab + (size_t)(lr + 64) * 512 + ko);
            fb0 = *(const float4*)(Bb + (size_t)lr * 512 + ko);
            fb1 = *(const float4*)(Bb + (size_t)(lr + 64) * 512 + ko);
        }
#pragma unroll
        for (int k = 0; k < 16; k++) {
            float4 a0 = *(const float4*)&As[k][tm * 8];
            float4 a1 = *(const float4*)&As[k][tm * 8 + 4];
            float4 b0 = *(const float4*)&Bs[k][tn * 8];
            float4 b1 = *(const float4*)&Bs[k][tn * 8 + 4];
            unsigned long long bb[4] = { pk2(b0.x, b0.y), pk2(b0.z, b0.w),
                                         pk2(b1.x, b1.y), pk2(b1.z, b1.w) };
            float av[8] = { a0.x, a0.y, a0.z, a0.w, a1.x, a1.y, a1.z, a1.w };
#pragma unroll
            for (int m = 0; m < 8; m++) {
                unsigned long long am = pk2(av[m], av[m]);
#pragma unroll
                for (int p = 0; p < 4; p++) c2[m][p] = fma2(am, bb[p], c2[m][p]);
            }
        }
        if (kt < 31) {
            __syncthreads();
            As[lc + 0][lr] = fa0.x; As[lc + 1][lr] = fa0.y; As[lc + 2][lr] = fa0.z; As[lc + 3][lr] = fa0.w;
            As[lc + 0][lr + 64] = fa1.x; As[lc + 1][lr + 64] = fa1.y; As[lc + 2][lr + 64] = fa1.z; As[lc + 3][lr + 64] = fa1.w;
            Bs[lc + 0][lr] = fb0.x; Bs[lc + 1][lr] = fb0.y; Bs[lc + 2][lr] = fb0.z; Bs[lc + 3][lr] = fb0.w;
            Bs[lc + 0][lr + 64] = fb1.x; Bs[lc + 1][lr + 64] = fb1.y; Bs[lc + 2][lr + 64] = fb1.z; Bs[lc + 3][lr + 64] = fb1.w;
            __syncthreads();
        }
    }

    // epilogue: add bias, store
    float bv[8];
#pragma unroll
    for (int p = 0; p < 8; p++) bv[p] = bias[nt * 128 + tn * 8 + p];
    float* Cb = C + (size_t)(mt * 128 + tm * 8) * ldc + nt * 128 + tn * 8;
#pragma unroll
    for (int m = 0; m < 8; m++) {
#pragma unroll
        for (int p = 0; p < 4; p++) {
            float x0, x1;
            upk2(c2[m][p], x0, x1);
            float2 o;
            o.x = x0 + bv[2 * p];
            o.y = x1 + bv[2 * p + 1];
            *(float2*)(Cb + (size_t)m * ldc + 2 * p) = o;
        }
    }
}

// ---------------- LIF over time (in-place h -> spikes) ---------------------
// Each thread owns one neuron (b, j); recurrence over t lives in a register.
__global__ void k_lif(int mode) {
    float* buf;
    int width;
    if (mode == 1) { buf = g_h1; width = H1n; } else { buf = g_h2; width = H2n; }
    size_t g = (size_t)blockIdx.x * blockDim.x + threadIdx.x;
    if (g >= (size_t)Bn * width) return;
    size_t step = (size_t)Bn * width;
    size_t idx = g;
    float v = 0.0f;
#pragma unroll 4
    for (int t = 0; t < Tn; t++) {
        float h = buf[idx];
        v = v + (h - v) * 0.5f;          // tau = 2.0, matches reference expr
        float s;
        if (v - 1.0f >= 0.0f) { s = 1.0f; v = 0.0f; }
        else                  { s = 0.0f; }
        buf[idx] = s;
        idx += step;
    }
}

// ---------------- output layer: GEMM3 + LIF3 + time-reduce -----------------
// One warp per batch row. Wo (5x256) held in registers, vo state in lane 0.
__global__ void k_out(const float* __restrict__ Wo, const float* __restrict__ bo,
                      float* __restrict__ out) {
    int warp = (blockIdx.x * blockDim.x + threadIdx.x) >> 5;
    int lane = threadIdx.x & 31;
    if (warp >= Bn) return;
    int b = warp;

    float w[On][8];
#pragma unroll
    for (int k = 0; k < On; k++)
#pragma unroll
        for (int i = 0; i < 8; i++) w[k][i] = Wo[k * H2n + lane + 32 * i];
    float bol[On];
#pragma unroll
    for (int k = 0; k < On; k++) bol[k] = bo[k];

    float vo[On];
    int cnt[On];
#pragma unroll
    for (int k = 0; k < On; k++) { vo[k] = 0.0f; cnt[k] = 0; }

    for (int t = 0; t < Tn; t++) {
        const float* s = g_h2 + ((size_t)t * Bn + b) * H2n;
        float sv[8];
#pragma unroll
        for (int i = 0; i < 8; i++) sv[i] = s[lane + 32 * i];
        float acc[On];
#pragma unroll
        for (int k = 0; k < On; k++) acc[k] = 0.0f;
#pragma unroll
        for (int i = 0; i < 8; i++)
#pragma unroll
            for (int k = 0; k < On; k++) acc[k] = fmaf(sv[i], w[k][i], acc[k]);
#pragma unroll
        for (int k = 0; k < On; k++) {
#pragma unroll
            for (int off = 16; off > 0; off >>= 1)
                acc[k] += __shfl_down_sync(0xffffffffu, acc[k], off);
        }
        if (lane == 0) {
#pragma unroll
            for (int k = 0; k < On; k++) {
                float o = acc[k] + bol[k];
                vo[k] = vo[k] + (o - vo[k]) * 0.5f;
                if (vo[k] - 1.0f >= 0.0f) { cnt[k]++; vo[k] = 0.0f; }
            }
        }
    }
    if (lane == 0) {
#pragma unroll
        for (int k = 0; k < On; k++)
            out[(size_t)b * On + k] = (float)cnt[k] / 100.0f;
    }
}

// ---------------------------------------------------------------------------
extern "C" void kernel_launch(void* const* d_in, const int* in_sizes, int n_in,
                              void* d_out, int out_size) {
    const float* x  = (const float*)d_in[0];   // (2048, 512, 100)
    const float* W1 = (const float*)d_in[1];   // (512, 512)
    const float* b1 = (const float*)d_in[2];   // (512)
    const float* W2 = (const float*)d_in[3];   // (256, 512)
    const float* b2 = (const float*)d_in[4];   // (256)
    const float* Wo = (const float*)d_in[5];   // (5, 256)
    const float* bo = (const float*)d_in[6];   // (5)
    float* out = (float*)d_out;                // (2048, 5)

    // 1) transpose x -> xT[(t*B+b)*N + n]
    k_transpose<<<dim3(Bn, Nin / 32, (Tn + 31) / 32), dim3(32, 8)>>>(x);
    // 2) h1 (all timesteps at once): (204800 x 512) = xT @ W1^T + b1
    k_gemm<<<dim3(H1n / 128, Mn / 128), 256>>>(W1, b1, H1n, 1);
    // 3) LIF layer 1 (in-place h1 -> s1)
    k_lif<<<(Bn * H1n) / 256, 256>>>(1);
    // 4) h2: (204800 x 256) = s1 @ W2^T + b2
    k_gemm<<<dim3(H2n / 128, Mn / 128), 256>>>(W2, b2, H2n, 2);
    // 5) LIF layer 2 (in-place h2 -> s2)
    k_lif<<<(Bn * H2n) / 256, 256>>>(2);
    // 6) output layer GEMM + LIF + spike-count reduce
    k_out<<<Bn / 8, 256>>>(Wo, bo, out);
}